// round 14
// baseline (speedup 1.0000x reference)
#include <cuda_runtime.h>
#include <cuda_bf16.h>
#include <cstdint>

typedef unsigned long long ull;

// Problem: x (8,256,128,128) f32 -> out (8,256,64,64) f32
// CARAFE downsample, decomposed:
//   compress: cx[b,h,w,cc] (bf16, px-major) = x * w_comp + b_comp   (tf32 mma GEMM)
//   encoder:  logit = 3x3-s2 conv(cx) * exp(p)                      (tf32 mma, bf16<<16)
//   softmax -> masks; aggregate: 25-tap s2 gather (direct-LDG, no smem)

// ---------------- compress geometry (M=256: 2 rows/block) ----------------
#define C_XP    264
#define C_XSF   8448                 // 32*264
#define C_WBP   36
#define C_WBSF  2304                 // 64*36
#define C_SMEMF (4*C_XSF + 4*C_WBSF + 64)
// ---------------- encoder geometry (bf16 staging) ----------------
#define E_CXP   72
#define E_SLOTS 297
#define E_CXH   (E_SLOTS * E_CXP)    // 21384 halves
#define E_WEP   584
#define E_WEH   (32 * E_WEP)         // 18688 halves
#define E_SMEMB (E_CXH*2 + E_WEH*2 + 128)

// ---- persistent device scratch ----
__device__ float g_wb[64 * 256];
__device__ __nv_bfloat16 g_web[32 * 576];
__device__ float g_bk[32];
__device__ float g_bc[64];
__device__ float g_mask[8 * 25 * 4096];
__device__ __nv_bfloat16 g_cx[8 * 128 * 128 * 64];

__device__ __forceinline__ ull pack2(float a, float b) {
    ull r; asm("mov.b64 %0, {%1, %2};" : "=l"(r) : "f"(a), "f"(b)); return r;
}
__device__ __forceinline__ void unpack2(ull v, float& a, float& b) {
    asm("mov.b64 {%0, %1}, %2;" : "=f"(a), "=f"(b) : "l"(v));
}
#define FMA2(d, a, b) asm("fma.rn.f32x2 %0, %1, %2, %0;" : "+l"(d) : "l"(a), "l"(b))

__device__ __forceinline__ uint32_t f2tf(float f) {
    uint32_t r; asm("cvt.rna.tf32.f32 %0, %1;" : "=r"(r) : "f"(f)); return r;
}
__device__ __forceinline__ void mma_tf32(float* d, const uint32_t* a, uint32_t b0, uint32_t b1) {
    asm volatile("mma.sync.aligned.m16n8k8.row.col.f32.tf32.tf32.f32 "
                 "{%0,%1,%2,%3}, {%4,%5,%6,%7}, {%8,%9}, {%0,%1,%2,%3};"
                 : "+f"(d[0]), "+f"(d[1]), "+f"(d[2]), "+f"(d[3])
                 : "r"(a[0]), "r"(a[1]), "r"(a[2]), "r"(a[3]), "r"(b0), "r"(b1));
}

__device__ __forceinline__ uint32_t smem_u32(const void* p) {
    return (uint32_t)__cvta_generic_to_shared(p);
}
__device__ __forceinline__ void cpa16(uint32_t dst, const void* src) {
    asm volatile("cp.async.ca.shared.global [%0], [%1], 16;" :: "r"(dst), "l"(src));
}
#define CP_COMMIT() asm volatile("cp.async.commit_group;")
template<int N> __device__ __forceinline__ void cp_wait() {
    asm volatile("cp.async.wait_group %0;" :: "n"(N));
}

// ============================================================================
// Kernel 1: prep. 96 blocks x 256 threads.
// ============================================================================
__global__ void prep_kernel(const float* __restrict__ w_comp, const float* __restrict__ b_comp,
                            const float* __restrict__ w_enc, const float* __restrict__ b_enc,
                            const float* __restrict__ power_p) {
    int bid = blockIdx.x, t = threadIdx.x;
    float expP = __expf(power_p[0]);
    if (bid < 64) {
        g_wb[bid * 256 + t] = __uint_as_float(f2tf(w_comp[bid * 256 + t]));
    } else {
        int n = bid - 64;
        for (int i = t; i < 576; i += 256) {
            float v = 0.f;
            if (n < 25) {
                int cc = i & 63, tap = i >> 6;
                v = w_enc[((n * 64 + cc) * 9) + tap] * expP;
            }
            g_web[n * 576 + i] = __float2bfloat16(v);
        }
        if (n == 0 && t < 32) g_bk[t] = (t < 25) ? b_enc[t] * expP : 0.f;
        if (n == 1 && t < 64) g_bc[t] = b_comp[t];
    }
}

// ============================================================================
// Kernel 2: compress GEMM. 512 blocks (2 rows each), 256 threads.
// M=256, N=64, K=256; tf32 m16n8k8; bf16 smem-staged coalesced output.
// ============================================================================
__global__ __launch_bounds__(256) void compress_kernel(const float* __restrict__ x) {
    extern __shared__ __align__(16) float SM[];
    int bid = blockIdx.x;
    int b = bid >> 6, h2 = bid & 63;
    int tid = threadIdx.x;
    int wid = tid >> 5, lane = tid & 31;
    int g = lane >> 2, tig = lane & 3;

    float* XS  = SM;
    float* WBS = SM + 4 * C_XSF;
    float* BC  = SM + 4 * C_XSF + 4 * C_WBSF;

    if (tid < 64) BC[tid] = g_bc[tid];

    uint32_t xsa = smem_u32(XS), wba = smem_u32(WBS);
    const float* xb = x + ((size_t)b * 256) * 16384 + h2 * 256;

    auto fill = [&](int s, int kc) {
        const float* xc = xb + (size_t)(kc * 32) * 16384;
        uint32_t xd = xsa + (uint32_t)s * (C_XSF * 4);
#pragma unroll
        for (int j = 0; j < 8; j++) {
            int idx = tid + j * 256;
            int c = idx >> 6, q = idx & 63;
            cpa16(xd + (uint32_t)(c * C_XP + 4 * q) * 4, xc + (size_t)c * 16384 + 4 * q);
        }
        uint32_t wd = wba + (uint32_t)s * (C_WBSF * 4);
#pragma unroll
        for (int j = 0; j < 2; j++) {
            int idx = tid + j * 256;
            int cc = idx >> 3, q = idx & 7;
            cpa16(wd + (uint32_t)(cc * C_WBP + 4 * q) * 4, g_wb + cc * 256 + kc * 32 + 4 * q);
        }
    };

    float d[2][8][4];
#pragma unroll
    for (int mt = 0; mt < 2; mt++)
#pragma unroll
        for (int nt = 0; nt < 8; nt++)
#pragma unroll
            for (int j = 0; j < 4; j++) d[mt][nt][j] = 0.f;

    fill(0, 0); CP_COMMIT();
    fill(1, 1); CP_COMMIT();
#pragma unroll 1
    for (int i = 0; i < 8; i++) {
        if (i + 2 < 8) fill((i + 2) & 3, i + 2);
        CP_COMMIT();
        cp_wait<2>();
        __syncthreads();

        const float* xs = XS + (i & 3) * C_XSF;
        const uint32_t* wbs = (const uint32_t*)(WBS + (i & 3) * C_WBSF);
#pragma unroll
        for (int k8 = 0; k8 < 4; k8++) {
            int cb = k8 * 8;
            uint32_t a[2][4];
#pragma unroll
            for (int mt = 0; mt < 2; mt++) {
                int pxl = 32 * wid + 16 * mt + g;
                a[mt][0] = f2tf(xs[(cb + tig) * C_XP + pxl]);
                a[mt][1] = f2tf(xs[(cb + tig) * C_XP + pxl + 8]);
                a[mt][2] = f2tf(xs[(cb + tig + 4) * C_XP + pxl]);
                a[mt][3] = f2tf(xs[(cb + tig + 4) * C_XP + pxl + 8]);
            }
#pragma unroll
            for (int nt = 0; nt < 8; nt++) {
                uint32_t b0 = wbs[(8 * nt + g) * C_WBP + cb + tig];
                uint32_t b1 = wbs[(8 * nt + g) * C_WBP + cb + tig + 4];
                mma_tf32(d[0][nt], a[0], b0, b1);
                mma_tf32(d[1][nt], a[1], b0, b1);
            }
        }
    }

    __syncthreads();
    uint32_t* CXT32 = (uint32_t*)SM;
#pragma unroll
    for (int mt = 0; mt < 2; mt++) {
#pragma unroll
        for (int nt = 0; nt < 8; nt++) {
            int pxl = 32 * wid + 16 * mt + g;
            int cc = 8 * nt + 2 * tig;
            float bc0 = BC[cc], bc1 = BC[cc + 1];
            __nv_bfloat162 p0 = __floats2bfloat162_rn(d[mt][nt][0] + bc0, d[mt][nt][1] + bc1);
            __nv_bfloat162 p1 = __floats2bfloat162_rn(d[mt][nt][2] + bc0, d[mt][nt][3] + bc1);
            CXT32[pxl * 32 + (cc >> 1)]       = *(uint32_t*)&p0;
            CXT32[(pxl + 8) * 32 + (cc >> 1)] = *(uint32_t*)&p1;
        }
    }
    __syncthreads();
    const uint4* srcq = (const uint4*)SM;
    uint4* dstq = (uint4*)(g_cx + (size_t)bid * 16384);
#pragma unroll
    for (int j = 0; j < 8; j++)
        dstq[tid + j * 256] = srcq[tid + j * 256];
}

// ============================================================================
// Kernel 3: encoder GEMM + softmax -> g_mask. 512 blocks, 128 threads.
// M=64 px, N=32, K=576. bf16 staging, tf32 mma via <<16.
// ============================================================================
__global__ __launch_bounds__(128) void encoder_kernel() {
    extern __shared__ __align__(16) char SMC[];
    unsigned short* CXS = (unsigned short*)SMC;
    unsigned short* WES = (unsigned short*)(SMC + E_CXH * 2);
    float* BKS = (float*)(SMC + E_CXH * 2 + E_WEH * 2);

    int bid = blockIdx.x;
    int b = bid >> 6, t = bid & 63;
    int w0 = (t & 3) * 16;
    int h0 = (t >> 2) * 4;
    int tid = threadIdx.x;
    int wid = tid >> 5, lane = tid & 31;
    int g = lane >> 2, tig = lane & 3;

    uint32_t* cz = (uint32_t*)CXS;
    for (int i = tid; i < E_CXH / 2; i += 128) cz[i] = 0u;
    if (tid < 32) BKS[tid] = g_bk[tid];
    __syncthreads();

    uint32_t cxa = smem_u32(CXS), wea = smem_u32(WES);
#pragma unroll 4
    for (int j = 0; j < 18; j++) {
        int idx = tid + j * 128;
        int n = idx / 72, q = idx - n * 72;
        cpa16(wea + (uint32_t)(n * E_WEP + 8 * q) * 2, g_web + n * 576 + 8 * q);
    }
#pragma unroll 4
    for (int j = 0; j < 19; j++) {
        int idx = tid + j * 128;
        if (idx < 2376) {
            int slot = idx >> 3, q = idx & 7;
            int r = slot / 33, pi = slot - r * 33;
            int hr = 2 * h0 - 1 + r;
            int wc = 2 * w0 - 1 + pi;
            if (hr >= 0 && hr < 128 && wc >= 0 && wc < 128)
                cpa16(cxa + (uint32_t)(slot * E_CXP + 8 * q) * 2,
                      g_cx + ((size_t)(b * 128 + hr) * 128 + wc) * 64 + 8 * q);
        }
    }
    CP_COMMIT();
    cp_wait<0>();
    __syncthreads();

    float d[4][4];
#pragma unroll
    for (int nt = 0; nt < 4; nt++)
#pragma unroll
        for (int j = 0; j < 4; j++) d[nt][j] = 0.f;

#pragma unroll 1
    for (int tap = 0; tap < 9; tap++) {
        int dy = tap / 3, dx = tap % 3;
        const unsigned short* baseL = CXS + ((2 * wid + dy) * 33 + (2 * g + dx)) * E_CXP;
        const unsigned short* baseH = baseL + 16 * E_CXP;
#pragma unroll
        for (int kc = 0; kc < 8; kc++) {
            int cb = kc * 8;
            uint32_t a[4];
            a[0] = ((uint32_t)baseL[cb + tig]) << 16;
            a[1] = ((uint32_t)baseH[cb + tig]) << 16;
            a[2] = ((uint32_t)baseL[cb + tig + 4]) << 16;
            a[3] = ((uint32_t)baseH[cb + tig + 4]) << 16;
            int ko = tap * 64 + cb + tig;
#pragma unroll
            for (int nt = 0; nt < 4; nt++) {
                uint32_t b0 = ((uint32_t)WES[(8 * nt + g) * E_WEP + ko]) << 16;
                uint32_t b1 = ((uint32_t)WES[(8 * nt + g) * E_WEP + ko + 4]) << 16;
                mma_tf32(d[nt], a, b0, b1);
            }
        }
    }

    int hh = h0 + wid;
#pragma unroll
    for (int half = 0; half < 2; half++) {
        int ww = w0 + g + 8 * half;
        float lg[8];
#pragma unroll
        for (int nt = 0; nt < 4; nt++) {
#pragma unroll
            for (int j = 0; j < 2; j++) {
                int n = 8 * nt + 2 * tig + j;
                float v = d[nt][2 * half + j];
                lg[nt * 2 + j] = (n < 25) ? (v + BKS[n]) : -1e30f;
            }
        }
        float mx = lg[0];
#pragma unroll
        for (int j = 1; j < 8; j++) mx = fmaxf(mx, lg[j]);
        mx = fmaxf(mx, __shfl_xor_sync(0xffffffffu, mx, 1));
        mx = fmaxf(mx, __shfl_xor_sync(0xffffffffu, mx, 2));
        float sum = 0.f;
#pragma unroll
        for (int j = 0; j < 8; j++) { lg[j] = __expf(lg[j] - mx); sum += lg[j]; }
        sum += __shfl_xor_sync(0xffffffffu, sum, 1);
        sum += __shfl_xor_sync(0xffffffffu, sum, 2);
        float inv = 1.f / sum;
#pragma unroll
        for (int nt = 0; nt < 4; nt++) {
#pragma unroll
            for (int j = 0; j < 2; j++) {
                int n = 8 * nt + 2 * tig + j;
                if (n < 25)
                    g_mask[((b * 25 + n) << 12) + (hh << 6) + ww] = lg[nt * 2 + j] * inv;
            }
        }
    }
}

// ============================================================================
// Kernel 4: aggregate via direct LDG (no smem, no syncs). 512 blocks
// (8b x 64 tiles of 16w x 4h), 256 threads = 8 warps; warp w owns channels
// {w, w+8, ...}. Lane = pxp(8) x pyq(4): px pair (wb, wb+1), row h0+pyq.
// Per channel: 5 rows x 4 LDG.64 (clamped addresses; OOB taps have zero
// masks so clamped values never contribute). L1/L2 absorb the 2.4x reuse.
// ============================================================================
__global__ __launch_bounds__(256) void aggregate_kernel(const float* __restrict__ x,
                                                        float* __restrict__ out) {
    int bid = blockIdx.x;
    int b = bid >> 6;
    int t = bid & 63;
    int w0 = (t & 3) << 4;
    int h0 = (t >> 2) << 2;
    int tid = threadIdx.x;
    int lane = tid & 31, warp = tid >> 5;
    int pxp = lane & 7, pyq = lane >> 3;
    int h = h0 + pyq;
    int wb = w0 + 2 * pxp;

    // ---- masks with OOB-tap zeroing (replaces x zero-padding exactly) ----
    ull mp[2][5][3];
#pragma unroll
    for (int e = 0; e < 2; e++) {
        int w = wb + e;
        float m[25];
#pragma unroll
        for (int k = 0; k < 25; k++)
            m[k] = g_mask[((b * 25 + k) << 12) + (h << 6) + w];
#pragma unroll
        for (int di = 0; di < 5; di++) {
            int r = 2 * h - 2 + di;
            bool rok = (r >= 0) && (r < 128);
            float mv[5];
#pragma unroll
            for (int dj = 0; dj < 5; dj++) {
                int col = 2 * w - 2 + dj;
                mv[dj] = (rok && col >= 0 && col < 128) ? m[di * 5 + dj] : 0.f;
            }
            mp[e][di][0] = pack2(mv[0], mv[1]);
            mp[e][di][1] = pack2(mv[2], mv[3]);
            mp[e][di][2] = pack2(mv[4], 0.f);
        }
    }

    // ---- clamped row/col offsets (values at clamped addrs are masked out) ----
    int ro[5];
#pragma unroll
    for (int di = 0; di < 5; di++) {
        int R = 2 * h - 2 + di;
        R = min(max(R, 0), 127);
        ro[di] = R << 7;
    }
    int co[4];
#pragma unroll
    for (int j = 0; j < 4; j++) {
        int c = 2 * wb - 2 + 2 * j;            // even -> 8B aligned
        co[j] = min(max(c, 0), 126);
    }

    const float* xb = x + (size_t)b * 256 * 16384;
    float* ob = out + (((size_t)b * 256) << 12) + (h << 6) + wb;

#pragma unroll 1
    for (int i = 0; i < 32; i++) {
        int c = warp + 8 * i;
        const float* xc = xb + ((size_t)c << 14);

        // load all 20 pairs first (MLP), then FMA
        ull v[5][4];
#pragma unroll
        for (int di = 0; di < 5; di++) {
#pragma unroll
            for (int j = 0; j < 4; j++)
                v[di][j] = *(const ull*)(xc + ro[di] + co[j]);
        }

        ull accA = 0ull, accB = 0ull;
#pragma unroll
        for (int di = 0; di < 5; di++) {
            // e=0 (w=wb):   cols 2wb-2..2wb+2 -> pairs v0,v1,v2
            FMA2(accA, mp[0][di][0], v[di][0]);
            FMA2(accA, mp[0][di][1], v[di][1]);
            FMA2(accA, mp[0][di][2], v[di][2]);
            // e=1 (w=wb+1): cols 2wb..2wb+4   -> pairs v1,v2,v3
            FMA2(accB, mp[1][di][0], v[di][1]);
            FMA2(accB, mp[1][di][1], v[di][2]);
            FMA2(accB, mp[1][di][2], v[di][3]);
        }
        float a0, a1, b0, b1;
        unpack2(accA, a0, a1);
        unpack2(accB, b0, b1);
        *(float2*)(ob + ((size_t)c << 12)) = make_float2(a0 + a1, b0 + b1);
    }
}

// ============================================================================
extern "C" void kernel_launch(void* const* d_in, const int* in_sizes, int n_in,
                              void* d_out, int out_size) {
    const float* x       = (const float*)d_in[0];
    const float* w_comp  = (const float*)d_in[1];
    const float* b_comp  = (const float*)d_in[2];
    const float* w_enc   = (const float*)d_in[3];
    const float* b_enc   = (const float*)d_in[4];
    const float* power_p = (const float*)d_in[5];
    float* out = (float*)d_out;

    cudaFuncSetAttribute(compress_kernel, cudaFuncAttributeMaxDynamicSharedMemorySize,
                         C_SMEMF * 4);
    cudaFuncSetAttribute(encoder_kernel, cudaFuncAttributeMaxDynamicSharedMemorySize,
                         E_SMEMB);

    prep_kernel<<<96, 256>>>(w_comp, b_comp, w_enc, b_enc, power_p);
    compress_kernel<<<512, 256, C_SMEMF * 4>>>(x);
    encoder_kernel<<<512, 128, E_SMEMB>>>();
    aggregate_kernel<<<512, 256>>>(x, out);
}

// round 16
// speedup vs baseline: 1.0988x; 1.0988x over previous
#include <cuda_runtime.h>
#include <cuda_bf16.h>
#include <cstdint>

typedef unsigned long long ull;

// Problem: x (8,256,128,128) f32 -> out (8,256,64,64) f32
// CARAFE downsample:
//   logits: FUSED (compressor o encoder) 3x3-s2 conv on x, tf32 mma, K=2304
//           + border-bias (btap) + softmax -> g_mask   [g_cx eliminated]
//   aggregate: 25-tap s2 gather, R11-proven block-synchronous LDS.128 scheme

// ---------------- fused logits geometry ----------------
#define F_PLANE  328                 // floats per channel plane (9*36 + 4 pad)
#define F_XSTG   2624                // 8 channels * F_PLANE
#define F_WSTG   1152                // u32 per weight stage (32 n x 36)
#define F_XCHUNK 648                 // 8ch * 9rows * 9quads
#define F_SMEMB  (4*F_XSTG*4 + 4*F_WSTG*4 + 288*4 + 32*4 + 16)
// ---------------- aggregate geometry (R11 verbatim) ----------------
#define A_CHF   760                  // 19 rows * 40 floats
#define A_STGF  6080                 // 8 channels per stage
#define A_NCHUNK 1520
#define A_SMEMF (4 * A_STGF)

// ---- persistent device scratch ----
// fused weights, bf16, K-permuted: idx = (n*32+chunk)*72 + tap*8 + tig*2 + hi
// so u32 pairs hold (k_cl=tig, k_cl=tig+4)
__device__ __align__(16) __nv_bfloat16 g_W2p[32 * 2304];
__device__ float g_btap[9 * 32];         // per-tap border bias (b_comp via encoder)
__device__ float g_bk[32];               // b_enc * expP
__device__ float g_mask[8 * 25 * 4096];

__device__ __forceinline__ ull pack2(float a, float b) {
    ull r; asm("mov.b64 %0, {%1, %2};" : "=l"(r) : "f"(a), "f"(b)); return r;
}
__device__ __forceinline__ void unpack2(ull v, float& a, float& b) {
    asm("mov.b64 {%0, %1}, %2;" : "=f"(a), "=f"(b) : "l"(v));
}
#define FMA2(d, a, b) asm("fma.rn.f32x2 %0, %1, %2, %0;" : "+l"(d) : "l"(a), "l"(b))

__device__ __forceinline__ uint32_t f2tf(float f) {
    uint32_t r; asm("cvt.rna.tf32.f32 %0, %1;" : "=r"(r) : "f"(f)); return r;
}
__device__ __forceinline__ void mma_tf32(float* d, const uint32_t* a, uint32_t b0, uint32_t b1) {
    asm volatile("mma.sync.aligned.m16n8k8.row.col.f32.tf32.tf32.f32 "
                 "{%0,%1,%2,%3}, {%4,%5,%6,%7}, {%8,%9}, {%0,%1,%2,%3};"
                 : "+f"(d[0]), "+f"(d[1]), "+f"(d[2]), "+f"(d[3])
                 : "r"(a[0]), "r"(a[1]), "r"(a[2]), "r"(a[3]), "r"(b0), "r"(b1));
}

__device__ __forceinline__ uint32_t smem_u32(const void* p) {
    return (uint32_t)__cvta_generic_to_shared(p);
}
__device__ __forceinline__ void cpa16(uint32_t dst, const void* src) {
    asm volatile("cp.async.ca.shared.global [%0], [%1], 16;" :: "r"(dst), "l"(src));
}
#define CP_COMMIT() asm volatile("cp.async.commit_group;")
template<int N> __device__ __forceinline__ void cp_wait() {
    asm volatile("cp.async.wait_group %0;" :: "n"(N));
}

// ============================================================================
// Kernel 1: prep — compose compressor x encoder weights into bf16 W2p + biases.
// 32 blocks (n, zero-padded past 25) x 256 threads (c).
// ============================================================================
__global__ void prep_kernel(const float* __restrict__ w_comp, const float* __restrict__ b_comp,
                            const float* __restrict__ w_enc, const float* __restrict__ b_enc,
                            const float* __restrict__ power_p) {
    int n = blockIdx.x;
    int c = threadIdx.x;
    __shared__ float we[9][64];     // [tap][cc]
    __shared__ float bc[64];
    float expP = __expf(power_p[0]);
    if (n < 25) {
        for (int i = c; i < 576; i += 256) {
            int cc = i / 9, tap = i % 9;
            we[tap][cc] = w_enc[n * 576 + i];
        }
    }
    if (c < 64) bc[c] = b_comp[c];
    __syncthreads();

    float wc[64];
#pragma unroll
    for (int cc = 0; cc < 64; cc++) wc[cc] = w_comp[cc * 256 + c];   // coalesced

    int chunk = c >> 3, cl = c & 7, tig = cl & 3, hi = cl >> 2;
#pragma unroll 1
    for (int tap = 0; tap < 9; tap++) {
        float s = 0.f;
        if (n < 25) {
#pragma unroll
            for (int cc = 0; cc < 64; cc++) s += we[tap][cc] * wc[cc];
            s *= expP;
        }
        g_W2p[(n * 32 + chunk) * 72 + tap * 8 + tig * 2 + hi] = __float2bfloat16(s);
    }
    if (c < 9) {
        float bs = 0.f;
        if (n < 25) {
            for (int cc = 0; cc < 64; cc++) bs += we[c][cc] * bc[cc];
            bs *= expP;
        }
        g_btap[c * 32 + n] = bs;
    }
    if (c == 9) g_bk[n] = (n < 25) ? b_enc[n] * expP : 0.f;
}

// ============================================================================
// Kernel 2: FUSED logits GEMM + border bias + softmax -> g_mask.
// 512 blocks (8b x 64 tiles of 16w x 4h), 128 threads (4 warps).
// M=64 px, N=32 (25 padded), K=2304 streamed as 32 chunks (8ch x 9taps,
// tap-major: each k-step of 8 = one tap). A from raw f32 x stages (cvt tf32);
// B from bf16 weight pairs (one LDS.32 -> b0=v<<16, b1=v&0xFFFF0000).
// 4-stage cp.async.
// ============================================================================
__global__ __launch_bounds__(128) void logits_kernel(const float* __restrict__ x) {
    extern __shared__ __align__(16) float SM[];
    float*    XS = SM;                               // 4 * F_XSTG floats
    uint32_t* WS = (uint32_t*)(SM + 4 * F_XSTG);     // 4 * F_WSTG u32
    float*    BT = SM + 4 * F_XSTG + 4 * F_WSTG;     // 288
    float*    BK = BT + 288;                         // 32

    int bid = blockIdx.x;
    int b = bid >> 6, t = bid & 63;
    int w0 = (t & 3) * 16;
    int h0 = (t >> 2) * 4;
    int tid = threadIdx.x;
    int wid = tid >> 5, lane = tid & 31;
    int g = lane >> 2, tig = lane & 3;

    for (int i = tid; i < 4 * F_XSTG; i += 128) XS[i] = 0.f;   // OOB slots stay zero
    for (int i = tid; i < 288; i += 128) BT[i] = g_btap[i];
    if (tid < 32) BK[tid] = g_bk[tid];

    // one-time x-fill addressing: 6 slots over 648 chunks
    int goff[6]; uint32_t soff[6]; unsigned vmask = 0;
#pragma unroll
    for (int j = 0; j < 6; j++) {
        int idx = tid + j * 128;
        goff[j] = 0; soff[j] = 0;
        if (idx < F_XCHUNK) {
            int ch = idx / 81; int rem = idx - ch * 81;
            int r = rem / 9, q = rem - r * 9;
            int row = 2 * h0 - 1 + r;          // 9 rows, origin 2h0-1
            int col = 2 * w0 - 4 + 4 * q;      // 9 quads, 16B-aligned origin
            if (row >= 0 && col >= 0) vmask |= 1u << j;   // whole-chunk validity
            goff[j] = ch * 16384 + (row << 7) + col;
            soff[j] = (uint32_t)((ch * F_PLANE + r * 36 + 4 * q) * 4);
        }
    }
    uint32_t xsa = smem_u32(XS), wsa = smem_u32(WS);
    const float* xb = x + (size_t)b * 256 * 16384;
    const uint32_t* wsrc = (const uint32_t*)g_W2p;

    auto fill = [&](int s, int ci) {
        const float* xc = xb + (size_t)(ci * 8) * 16384;
        uint32_t xd = xsa + (uint32_t)s * (F_XSTG * 4);
#pragma unroll
        for (int j = 0; j < 6; j++)
            if (vmask & (1u << j)) cpa16(xd + soff[j], xc + goff[j]);
        uint32_t wd = wsa + (uint32_t)s * (F_WSTG * 4);
#pragma unroll
        for (int j = 0; j < 3; j++) {
            int idx = tid + j * 128;
            if (idx < 288) {
                int nn = idx / 9, q = idx - nn * 9;
                cpa16(wd + (uint32_t)(nn * 36 + 4 * q) * 4,
                      wsrc + (size_t)(nn * 32 + ci) * 36 + 4 * q);
            }
        }
    };

    float d[4][4];
#pragma unroll
    for (int nt = 0; nt < 4; nt++)
#pragma unroll
        for (int j = 0; j < 4; j++) d[nt][j] = 0.f;

    __syncthreads();                 // zeros visible
    fill(0, 0); CP_COMMIT();
    fill(1, 1); CP_COMMIT();
#pragma unroll 1
    for (int i = 0; i < 32; i++) {
        if (i + 2 < 32) fill((i + 2) & 3, i + 2);
        CP_COMMIT();
        cp_wait<2>();
        __syncthreads();

        const float* xs = XS + (i & 3) * F_XSTG;
        const uint32_t* ws = WS + (i & 3) * F_WSTG;
#pragma unroll
        for (int tap = 0; tap < 9; tap++) {
            int dy = tap / 3, dx = tap % 3;
            int roff = (2 * wid + dy) * 36;
            int c0 = 2 * g + dx + 3;
            uint32_t a[4];
            a[0] = f2tf(xs[tig * F_PLANE + roff + c0]);          // m=g,   k=cl=tig
            a[1] = f2tf(xs[tig * F_PLANE + roff + c0 + 16]);     // m=g+8
            a[2] = f2tf(xs[(tig + 4) * F_PLANE + roff + c0]);    // k=cl=tig+4
            a[3] = f2tf(xs[(tig + 4) * F_PLANE + roff + c0 + 16]);
#pragma unroll
            for (int nt = 0; nt < 4; nt++) {
                uint32_t v = ws[(8 * nt + g) * 36 + tap * 4 + tig];
                mma_tf32(d[nt], a, v << 16, v & 0xFFFF0000u);
            }
        }
    }

    // epilogue: bk + border btap + softmax (proven scheme)
    int hh = h0 + wid;
#pragma unroll
    for (int half = 0; half < 2; half++) {
        int ww = w0 + g + 8 * half;
        float lg[8];
#pragma unroll
        for (int nt = 0; nt < 4; nt++) {
#pragma unroll
            for (int j = 0; j < 2; j++) {
                int n = 8 * nt + 2 * tig + j;
                lg[2 * nt + j] = (n < 25) ? (d[nt][2 * half + j] + BK[n]) : -1e30f;
            }
        }
#pragma unroll
        for (int tap = 0; tap < 9; tap++) {
            int dy = tap / 3, dx = tap % 3;
            bool inb = (2 * hh - 1 + dy >= 0) && (2 * ww - 1 + dx >= 0) && (2 * ww - 1 + dx < 128);
            if (inb) {
#pragma unroll
                for (int nt = 0; nt < 4; nt++)
#pragma unroll
                    for (int j = 0; j < 2; j++)
                        lg[2 * nt + j] += BT[tap * 32 + 8 * nt + 2 * tig + j];  // 0 for n>=25
            }
        }
        float mx = lg[0];
#pragma unroll
        for (int j = 1; j < 8; j++) mx = fmaxf(mx, lg[j]);
        mx = fmaxf(mx, __shfl_xor_sync(0xffffffffu, mx, 1));
        mx = fmaxf(mx, __shfl_xor_sync(0xffffffffu, mx, 2));
        float sum = 0.f;
#pragma unroll
        for (int j = 0; j < 8; j++) { lg[j] = __expf(lg[j] - mx); sum += lg[j]; }
        sum += __shfl_xor_sync(0xffffffffu, sum, 1);
        sum += __shfl_xor_sync(0xffffffffu, sum, 2);
        float inv = 1.f / sum;
#pragma unroll
        for (int nt = 0; nt < 4; nt++) {
#pragma unroll
            for (int j = 0; j < 2; j++) {
                int n = 8 * nt + 2 * tig + j;
                if (n < 25)
                    g_mask[((b * 25 + n) << 12) + (hh << 6) + ww] = lg[2 * nt + j] * inv;
            }
        }
    }
}

// ============================================================================
// Kernel 3: aggregate — R11-proven (71.3us). 256 blocks (8b x 32 tiles of
// 16w x 8h), 256 threads: pxp(8) x ccs(4) x py(8). 8 ch/stage, 32 iters,
// 4-stage cp.async, LDS.128 consume scheme.
// ============================================================================
__global__ __launch_bounds__(256) void aggregate_kernel(const float* __restrict__ x,
                                                        float* __restrict__ out) {
    extern __shared__ __align__(16) float AS[];
    int bid = blockIdx.x;
    int b = bid >> 5;
    int t = bid & 31;
    int w0 = (t & 3) * 16;
    int h0 = (t >> 2) * 8;
    int tid = threadIdx.x;
    int pxp = tid & 7;
    int ccs = (tid >> 3) & 3;
    int py  = tid >> 5;
    int h = h0 + py;
    int wbase = w0 + 2 * pxp;

    for (int i = tid; i < A_SMEMF; i += 256) AS[i] = 0.f;

    uint32_t asa = smem_u32(AS);
    const float* xb = x + (size_t)b * 256 * 16384;

    ull mp[2][5][3];
#pragma unroll
    for (int e = 0; e < 2; e++) {
        int w = wbase + e;
        float m[25];
#pragma unroll
        for (int k = 0; k < 25; k++)
            m[k] = g_mask[((b * 25 + k) << 12) + (h << 6) + w];
#pragma unroll
        for (int di = 0; di < 5; di++) {
            mp[e][di][0] = pack2(m[5 * di],     m[5 * di + 1]);
            mp[e][di][1] = pack2(m[5 * di + 2], m[5 * di + 3]);
            mp[e][di][2] = pack2(m[5 * di + 4], 0.f);
        }
    }

    auto fill = [&](int s, int ci) {
        const float* xc = xb + (size_t)(8 * ci) * 16384;
        uint32_t base = asa + (uint32_t)s * (A_STGF * 4);
#pragma unroll
        for (int j = 0; j < 6; j++) {
            int idx = tid + j * 256;
            if (idx < A_NCHUNK) {
                int ch = idx / 190; int rem = idx - ch * 190;
                int r = rem / 10;   int q = rem - r * 10;
                int row = 2 * h0 - 2 + r;
                int col = 2 * w0 - 4 + 4 * q;
                if (row >= 0 && row < 128 && col >= 0 && col <= 124)
                    cpa16(base + (uint32_t)(ch * A_CHF + r * 40 + 4 * q) * 4,
                          xc + (size_t)ch * 16384 + (row << 7) + col);
            }
        }
    };

    float* ob = out + (((size_t)b * 256) << 12) + (h << 6) + wbase;
    __syncthreads();
    fill(0, 0); CP_COMMIT();
    fill(1, 1); CP_COMMIT();

#pragma unroll 1
    for (int i = 0; i < 32; i++) {
        if (i + 2 < 32) fill((i + 2) & 3, i + 2);
        CP_COMMIT();
        cp_wait<2>();
        __syncthreads();

        const float* rp = AS + (i & 3) * A_STGF;
#pragma unroll
        for (int sub = 0; sub < 2; sub++) {
            int ch = ccs + 4 * sub;
            const float* cpp = rp + ch * A_CHF + 4 * pxp;
            ull accA = 0ull, accB = 0ull;
#pragma unroll
            for (int di = 0; di < 5; di++) {
                const float* rr = cpp + (2 * py + di) * 40;
                ulonglong2 q0 = *(const ulonglong2*)(rr);       // f0..f3
                ulonglong2 q1 = *(const ulonglong2*)(rr + 4);   // f4..f7
                ull d2 = *(const ull*)(rr + 8);                 // f8,f9
                FMA2(accA, mp[0][di][0], q0.y);
                FMA2(accA, mp[0][di][1], q1.x);
                FMA2(accA, mp[0][di][2], q1.y);
                FMA2(accB, mp[1][di][0], q1.x);
                FMA2(accB, mp[1][di][1], q1.y);
                FMA2(accB, mp[1][di][2], d2);
            }
            float a0, a1, b0, b1;
            unpack2(accA, a0, a1);
            unpack2(accB, b0, b1);
            *(float2*)(ob + ((size_t)(8 * i + ch) << 12)) = make_float2(a0 + a1, b0 + b1);
        }
    }
}

// ============================================================================
extern "C" void kernel_launch(void* const* d_in, const int* in_sizes, int n_in,
                              void* d_out, int out_size) {
    const float* x       = (const float*)d_in[0];
    const float* w_comp  = (const float*)d_in[1];
    const float* b_comp  = (const float*)d_in[2];
    const float* w_enc   = (const float*)d_in[3];
    const float* b_enc   = (const float*)d_in[4];
    const float* power_p = (const float*)d_in[5];
    float* out = (float*)d_out;

    cudaFuncSetAttribute(logits_kernel, cudaFuncAttributeMaxDynamicSharedMemorySize,
                         F_SMEMB);
    cudaFuncSetAttribute(aggregate_kernel, cudaFuncAttributeMaxDynamicSharedMemorySize,
                         A_SMEMF * 4);

    prep_kernel<<<32, 256>>>(w_comp, b_comp, w_enc, b_enc, power_p);
    logits_kernel<<<512, 128, F_SMEMB>>>(x);
    aggregate_kernel<<<256, 256, A_SMEMF * 4>>>(x, out);
}

// round 17
// speedup vs baseline: 1.3488x; 1.2276x over previous
#include <cuda_runtime.h>
#include <cuda_bf16.h>
#include <cstdint>

typedef unsigned long long ull;

// Problem: x (8,256,128,128) f32 -> out (8,256,64,64) f32
// CARAFE downsample, decomposed (R11 structure, compress re-tiled):
//   compress: cx[b,h,w,cc] (bf16, px-major) = x * w_comp + b_comp   (tf32 mma, bf16 W pairs)
//   encoder:  logit = 3x3-s2 conv(cx) * exp(p)                      (tf32 mma, bf16<<16)
//   softmax -> masks; aggregate: 25-tap s2 gather (R11 LDS.128 scheme)

// ---------------- compress geometry (M=256, 16-ch chunks, 2 blocks/SM) ------
#define C_XP    264
#define C_XSTG  4224                 // 16 ch * 264 floats per stage
#define C_WP    20                   // u32 pitch per cc (bank-distinct: 20g+tig)
#define C_WSTG  1280                 // 64 cc * 20 u32 per stage
#define C_SMEMB ((4*C_XSTG + 64) * 4 + 4*C_WSTG*4)   // 88320 B
// ---------------- encoder geometry (bf16 staging, R11 verbatim) -------------
#define E_CXP   72
#define E_SLOTS 297
#define E_CXH   (E_SLOTS * E_CXP)    // 21384 halves
#define E_WEP   584
#define E_WEH   (32 * E_WEP)         // 18688 halves
#define E_SMEMB (E_CXH*2 + E_WEH*2 + 128)
// ---------------- aggregate geometry (R11 verbatim) -------------------------
#define A_CHF   760                  // 19 rows * 40 floats
#define A_STGF  6080                 // 8 channels per stage
#define A_NCHUNK 1520
#define A_SMEMF (4 * A_STGF)

// ---- persistent device scratch ----
__device__ uint32_t g_wbp[16 * 512];          // packed bf16 w_comp pairs: [kc][cc*8 + k8*4 + tig]
__device__ __nv_bfloat16 g_web[32 * 576];     // bf16 w_enc*expP, [n][tap*64+cc]
__device__ float g_bk[32];
__device__ float g_bc[64];
__device__ float g_mask[8 * 25 * 4096];
__device__ __nv_bfloat16 g_cx[8 * 128 * 128 * 64];   // compressed feats, px-major

__device__ __forceinline__ ull pack2(float a, float b) {
    ull r; asm("mov.b64 %0, {%1, %2};" : "=l"(r) : "f"(a), "f"(b)); return r;
}
__device__ __forceinline__ void unpack2(ull v, float& a, float& b) {
    asm("mov.b64 {%0, %1}, %2;" : "=f"(a), "=f"(b) : "l"(v));
}
#define FMA2(d, a, b) asm("fma.rn.f32x2 %0, %1, %2, %0;" : "+l"(d) : "l"(a), "l"(b))

__device__ __forceinline__ uint32_t f2tf(float f) {
    uint32_t r; asm("cvt.rna.tf32.f32 %0, %1;" : "=r"(r) : "f"(f)); return r;
}
__device__ __forceinline__ void mma_tf32(float* d, const uint32_t* a, uint32_t b0, uint32_t b1) {
    asm volatile("mma.sync.aligned.m16n8k8.row.col.f32.tf32.tf32.f32 "
                 "{%0,%1,%2,%3}, {%4,%5,%6,%7}, {%8,%9}, {%0,%1,%2,%3};"
                 : "+f"(d[0]), "+f"(d[1]), "+f"(d[2]), "+f"(d[3])
                 : "r"(a[0]), "r"(a[1]), "r"(a[2]), "r"(a[3]), "r"(b0), "r"(b1));
}

__device__ __forceinline__ uint32_t smem_u32(const void* p) {
    return (uint32_t)__cvta_generic_to_shared(p);
}
__device__ __forceinline__ void cpa16(uint32_t dst, const void* src) {
    asm volatile("cp.async.ca.shared.global [%0], [%1], 16;" :: "r"(dst), "l"(src));
}
#define CP_COMMIT() asm volatile("cp.async.commit_group;")
template<int N> __device__ __forceinline__ void cp_wait() {
    asm volatile("cp.async.wait_group %0;" :: "n"(N));
}

// ============================================================================
// Kernel 1: prep. 96 blocks x 256 threads.
//  blocks 0..63 (cc): pack w_comp into bf16 (k,k+4) u32 pairs.
//  blocks 64..95 (n): g_web bf16 + biases.
// ============================================================================
__global__ void prep_kernel(const float* __restrict__ w_comp, const float* __restrict__ b_comp,
                            const float* __restrict__ w_enc, const float* __restrict__ b_enc,
                            const float* __restrict__ power_p) {
    int bid = blockIdx.x, t = threadIdx.x;
    float expP = __expf(power_p[0]);
    if (bid < 64) {
        int cc = bid;
        if (t < 128) {
            int kc = t >> 3, rem = t & 7, k8 = rem >> 2, tig = rem & 3;
            int c_lo = kc * 16 + k8 * 8 + tig;
            __nv_bfloat16 lo = __float2bfloat16(w_comp[cc * 256 + c_lo]);
            __nv_bfloat16 hi = __float2bfloat16(w_comp[cc * 256 + c_lo + 4]);
            uint32_t v = ((uint32_t)(*(unsigned short*)&hi) << 16) | (uint32_t)(*(unsigned short*)&lo);
            g_wbp[kc * 512 + cc * 8 + rem] = v;
        }
    } else {
        int n = bid - 64;
        for (int i = t; i < 576; i += 256) {
            float v = 0.f;
            if (n < 25) {
                int cc = i & 63, tap = i >> 6;
                v = w_enc[((n * 64 + cc) * 9) + tap] * expP;
            }
            g_web[n * 576 + i] = __float2bfloat16(v);
        }
        if (n == 0 && t < 32) g_bk[t] = (t < 25) ? b_enc[t] * expP : 0.f;
        if (n == 1 && t < 64) g_bc[t] = b_comp[t];
    }
}

// ============================================================================
// Kernel 2: compress GEMM. 512 blocks (2 rows each), 256 threads, 2 blocks/SM.
// M=256, N=64, K=256 in 16 chunks of 16 ch; tf32 m16n8k8; B from packed bf16
// pairs (1 LDS.32 -> b0=v<<16, b1=v&0xFFFF0000). bf16 smem-staged output.
// ============================================================================
__global__ __launch_bounds__(256) void compress_kernel(const float* __restrict__ x) {
    extern __shared__ __align__(16) float SM[];
    int bid = blockIdx.x;
    int b = bid >> 6, h2 = bid & 63;
    int tid = threadIdx.x;
    int wid = tid >> 5, lane = tid & 31;
    int g = lane >> 2, tig = lane & 3;

    float*    XS  = SM;                           // 4 stages of [16 c][264]
    uint32_t* WBS = (uint32_t*)(SM + 4 * C_XSTG); // 4 stages of [64 cc][20] u32
    float*    BC  = SM + 4 * C_XSTG + 4 * C_WSTG;

    if (tid < 64) BC[tid] = g_bc[tid];

    uint32_t xsa = smem_u32(XS), wba = smem_u32(WBS);
    const float* xb = x + ((size_t)b * 256) * 16384 + h2 * 256;   // 2 rows contiguous

    auto fill = [&](int s, int kc) {              // kc: chunk of 16 channels
        const float* xc = xb + (size_t)(kc * 16) * 16384;
        uint32_t xd = xsa + (uint32_t)s * (C_XSTG * 4);
#pragma unroll
        for (int j = 0; j < 4; j++) {
            int idx = tid + j * 256;
            int c = idx >> 6, q = idx & 63;
            cpa16(xd + (uint32_t)(c * C_XP + 4 * q) * 4, xc + (size_t)c * 16384 + 4 * q);
        }
        if (tid < 128) {
            int cc = tid >> 1, k8 = tid & 1;
            uint32_t wd = wba + (uint32_t)s * (C_WSTG * 4);
            cpa16(wd + (uint32_t)(cc * C_WP + k8 * 4) * 4,
                  g_wbp + kc * 512 + cc * 8 + k8 * 4);
        }
    };

    float d[2][8][4];
#pragma unroll
    for (int mt = 0; mt < 2; mt++)
#pragma unroll
        for (int nt = 0; nt < 8; nt++)
#pragma unroll
            for (int j = 0; j < 4; j++) d[mt][nt][j] = 0.f;

    fill(0, 0); CP_COMMIT();
    fill(1, 1); CP_COMMIT();
#pragma unroll 1
    for (int i = 0; i < 16; i++) {
        if (i + 2 < 16) fill((i + 2) & 3, i + 2);
        CP_COMMIT();
        cp_wait<2>();
        __syncthreads();

        const float* xs = XS + (i & 3) * C_XSTG;
        const uint32_t* ws = WBS + (i & 3) * C_WSTG;
#pragma unroll
        for (int k8 = 0; k8 < 2; k8++) {
            int cb = k8 * 8;
            uint32_t a[2][4];
#pragma unroll
            for (int mt = 0; mt < 2; mt++) {
                int pxl = 32 * wid + 16 * mt + g;
                a[mt][0] = f2tf(xs[(cb + tig) * C_XP + pxl]);
                a[mt][1] = f2tf(xs[(cb + tig) * C_XP + pxl + 8]);
                a[mt][2] = f2tf(xs[(cb + tig + 4) * C_XP + pxl]);
                a[mt][3] = f2tf(xs[(cb + tig + 4) * C_XP + pxl + 8]);
            }
#pragma unroll
            for (int nt = 0; nt < 8; nt++) {
                uint32_t v = ws[(8 * nt + g) * C_WP + k8 * 4 + tig];
                uint32_t b0 = v << 16, b1 = v & 0xFFFF0000u;
                mma_tf32(d[0][nt], a[0], b0, b1);
                mma_tf32(d[1][nt], a[1], b0, b1);
            }
        }
    }

    // epilogue (R11 verbatim): bf16 tile in smem, then coalesced 16B stores
    __syncthreads();
    uint32_t* CXT32 = (uint32_t*)SM;
#pragma unroll
    for (int mt = 0; mt < 2; mt++) {
#pragma unroll
        for (int nt = 0; nt < 8; nt++) {
            int pxl = 32 * wid + 16 * mt + g;
            int cc = 8 * nt + 2 * tig;
            float bc0 = BC[cc], bc1 = BC[cc + 1];
            __nv_bfloat162 p0 = __floats2bfloat162_rn(d[mt][nt][0] + bc0, d[mt][nt][1] + bc1);
            __nv_bfloat162 p1 = __floats2bfloat162_rn(d[mt][nt][2] + bc0, d[mt][nt][3] + bc1);
            CXT32[pxl * 32 + (cc >> 1)]       = *(uint32_t*)&p0;
            CXT32[(pxl + 8) * 32 + (cc >> 1)] = *(uint32_t*)&p1;
        }
    }
    __syncthreads();
    const uint4* srcq = (const uint4*)SM;
    uint4* dstq = (uint4*)(g_cx + (size_t)bid * 16384);
#pragma unroll
    for (int j = 0; j < 8; j++)
        dstq[tid + j * 256] = srcq[tid + j * 256];
}

// ============================================================================
// Kernel 3: encoder GEMM + softmax -> g_mask (R11 verbatim). 512 blocks,
// 128 threads. M=64 px, N=32, K=576. bf16 staging, tf32 mma via <<16.
// ============================================================================
__global__ __launch_bounds__(128) void encoder_kernel() {
    extern __shared__ __align__(16) char SMC[];
    unsigned short* CXS = (unsigned short*)SMC;
    unsigned short* WES = (unsigned short*)(SMC + E_CXH * 2);
    float* BKS = (float*)(SMC + E_CXH * 2 + E_WEH * 2);

    int bid = blockIdx.x;
    int b = bid >> 6, t = bid & 63;
    int w0 = (t & 3) * 16;
    int h0 = (t >> 2) * 4;
    int tid = threadIdx.x;
    int wid = tid >> 5, lane = tid & 31;
    int g = lane >> 2, tig = lane & 3;

    uint32_t* cz = (uint32_t*)CXS;
    for (int i = tid; i < E_CXH / 2; i += 128) cz[i] = 0u;
    if (tid < 32) BKS[tid] = g_bk[tid];
    __syncthreads();

    uint32_t cxa = smem_u32(CXS), wea = smem_u32(WES);
#pragma unroll 4
    for (int j = 0; j < 18; j++) {
        int idx = tid + j * 128;
        int n = idx / 72, q = idx - n * 72;
        cpa16(wea + (uint32_t)(n * E_WEP + 8 * q) * 2, g_web + n * 576 + 8 * q);
    }
#pragma unroll 4
    for (int j = 0; j < 19; j++) {
        int idx = tid + j * 128;
        if (idx < 2376) {
            int slot = idx >> 3, q = idx & 7;
            int r = slot / 33, pi = slot - r * 33;
            int hr = 2 * h0 - 1 + r;
            int wc = 2 * w0 - 1 + pi;
            if (hr >= 0 && hr < 128 && wc >= 0 && wc < 128)
                cpa16(cxa + (uint32_t)(slot * E_CXP + 8 * q) * 2,
                      g_cx + ((size_t)(b * 128 + hr) * 128 + wc) * 64 + 8 * q);
        }
    }
    CP_COMMIT();
    cp_wait<0>();
    __syncthreads();

    float d[4][4];
#pragma unroll
    for (int nt = 0; nt < 4; nt++)
#pragma unroll
        for (int j = 0; j < 4; j++) d[nt][j] = 0.f;

#pragma unroll 1
    for (int tap = 0; tap < 9; tap++) {
        int dy = tap / 3, dx = tap % 3;
        const unsigned short* baseL = CXS + ((2 * wid + dy) * 33 + (2 * g + dx)) * E_CXP;
        const unsigned short* baseH = baseL + 16 * E_CXP;
#pragma unroll
        for (int kc = 0; kc < 8; kc++) {
            int cb = kc * 8;
            uint32_t a[4];
            a[0] = ((uint32_t)baseL[cb + tig]) << 16;
            a[1] = ((uint32_t)baseH[cb + tig]) << 16;
            a[2] = ((uint32_t)baseL[cb + tig + 4]) << 16;
            a[3] = ((uint32_t)baseH[cb + tig + 4]) << 16;
            int ko = tap * 64 + cb + tig;
#pragma unroll
            for (int nt = 0; nt < 4; nt++) {
                uint32_t b0 = ((uint32_t)WES[(8 * nt + g) * E_WEP + ko]) << 16;
                uint32_t b1 = ((uint32_t)WES[(8 * nt + g) * E_WEP + ko + 4]) << 16;
                mma_tf32(d[nt], a, b0, b1);
            }
        }
    }

    int hh = h0 + wid;
#pragma unroll
    for (int half = 0; half < 2; half++) {
        int ww = w0 + g + 8 * half;
        float lg[8];
#pragma unroll
        for (int nt = 0; nt < 4; nt++) {
#pragma unroll
            for (int j = 0; j < 2; j++) {
                int n = 8 * nt + 2 * tig + j;
                float v = d[nt][2 * half + j];
                lg[nt * 2 + j] = (n < 25) ? (v + BKS[n]) : -1e30f;
            }
        }
        float mx = lg[0];
#pragma unroll
        for (int j = 1; j < 8; j++) mx = fmaxf(mx, lg[j]);
        mx = fmaxf(mx, __shfl_xor_sync(0xffffffffu, mx, 1));
        mx = fmaxf(mx, __shfl_xor_sync(0xffffffffu, mx, 2));
        float sum = 0.f;
#pragma unroll
        for (int j = 0; j < 8; j++) { lg[j] = __expf(lg[j] - mx); sum += lg[j]; }
        sum += __shfl_xor_sync(0xffffffffu, sum, 1);
        sum += __shfl_xor_sync(0xffffffffu, sum, 2);
        float inv = 1.f / sum;
#pragma unroll
        for (int nt = 0; nt < 4; nt++) {
#pragma unroll
            for (int j = 0; j < 2; j++) {
                int n = 8 * nt + 2 * tig + j;
                if (n < 25)
                    g_mask[((b * 25 + n) << 12) + (hh << 6) + ww] = lg[nt * 2 + j] * inv;
            }
        }
    }
}

// ============================================================================
// Kernel 4: aggregate (R11 verbatim, 71.3us). 256 blocks (8b x 32 tiles of
// 16w x 8h), 256 threads: pxp(8) x ccs(4) x py(8). 8 ch/stage, 32 iters,
// 4-stage cp.async, LDS.128 consume scheme.
// ============================================================================
__global__ __launch_bounds__(256) void aggregate_kernel(const float* __restrict__ x,
                                                        float* __restrict__ out) {
    extern __shared__ __align__(16) float AS[];
    int bid = blockIdx.x;
    int b = bid >> 5;
    int t = bid & 31;
    int w0 = (t & 3) * 16;
    int h0 = (t >> 2) * 8;
    int tid = threadIdx.x;
    int pxp = tid & 7;
    int ccs = (tid >> 3) & 3;
    int py  = tid >> 5;
    int h = h0 + py;
    int wbase = w0 + 2 * pxp;

    for (int i = tid; i < A_SMEMF; i += 256) AS[i] = 0.f;

    uint32_t asa = smem_u32(AS);
    const float* xb = x + (size_t)b * 256 * 16384;

    ull mp[2][5][3];
#pragma unroll
    for (int e = 0; e < 2; e++) {
        int w = wbase + e;
        float m[25];
#pragma unroll
        for (int k = 0; k < 25; k++)
            m[k] = g_mask[((b * 25 + k) << 12) + (h << 6) + w];
#pragma unroll
        for (int di = 0; di < 5; di++) {
            mp[e][di][0] = pack2(m[5 * di],     m[5 * di + 1]);
            mp[e][di][1] = pack2(m[5 * di + 2], m[5 * di + 3]);
            mp[e][di][2] = pack2(m[5 * di + 4], 0.f);
        }
    }

    auto fill = [&](int s, int ci) {
        const float* xc = xb + (size_t)(8 * ci) * 16384;
        uint32_t base = asa + (uint32_t)s * (A_STGF * 4);
#pragma unroll
        for (int j = 0; j < 6; j++) {
            int idx = tid + j * 256;
            if (idx < A_NCHUNK) {
                int ch = idx / 190; int rem = idx - ch * 190;
                int r = rem / 10;   int q = rem - r * 10;
                int row = 2 * h0 - 2 + r;
                int col = 2 * w0 - 4 + 4 * q;
                if (row >= 0 && row < 128 && col >= 0 && col <= 124)
                    cpa16(base + (uint32_t)(ch * A_CHF + r * 40 + 4 * q) * 4,
                          xc + (size_t)ch * 16384 + (row << 7) + col);
            }
        }
    };

    float* ob = out + (((size_t)b * 256) << 12) + (h << 6) + wbase;
    __syncthreads();
    fill(0, 0); CP_COMMIT();
    fill(1, 1); CP_COMMIT();

#pragma unroll 1
    for (int i = 0; i < 32; i++) {
        if (i + 2 < 32) fill((i + 2) & 3, i + 2);
        CP_COMMIT();
        cp_wait<2>();
        __syncthreads();

        const float* rp = AS + (i & 3) * A_STGF;
#pragma unroll
        for (int sub = 0; sub < 2; sub++) {
            int ch = ccs + 4 * sub;
            const float* cpp = rp + ch * A_CHF + 4 * pxp;
            ull accA = 0ull, accB = 0ull;
#pragma unroll
            for (int di = 0; di < 5; di++) {
                const float* rr = cpp + (2 * py + di) * 40;
                ulonglong2 q0 = *(const ulonglong2*)(rr);       // f0..f3
                ulonglong2 q1 = *(const ulonglong2*)(rr + 4);   // f4..f7
                ull d2 = *(const ull*)(rr + 8);                 // f8,f9
                FMA2(accA, mp[0][di][0], q0.y);
                FMA2(accA, mp[0][di][1], q1.x);
                FMA2(accA, mp[0][di][2], q1.y);
                FMA2(accB, mp[1][di][0], q1.x);
                FMA2(accB, mp[1][di][1], q1.y);
                FMA2(accB, mp[1][di][2], d2);
            }
            float a0, a1, b0, b1;
            unpack2(accA, a0, a1);
            unpack2(accB, b0, b1);
            *(float2*)(ob + ((size_t)(8 * i + ch) << 12)) = make_float2(a0 + a1, b0 + b1);
        }
    }
}

// ============================================================================
extern "C" void kernel_launch(void* const* d_in, const int* in_sizes, int n_in,
                              void* d_out, int out_size) {
    const float* x       = (const float*)d_in[0];
    const float* w_comp  = (const float*)d_in[1];
    const float* b_comp  = (const float*)d_in[2];
    const float* w_enc   = (const float*)d_in[3];
    const float* b_enc   = (const float*)d_in[4];
    const float* power_p = (const float*)d_in[5];
    float* out = (float*)d_out;

    cudaFuncSetAttribute(compress_kernel, cudaFuncAttributeMaxDynamicSharedMemorySize,
                         C_SMEMB);
    cudaFuncSetAttribute(encoder_kernel, cudaFuncAttributeMaxDynamicSharedMemorySize,
                         E_SMEMB);
    cudaFuncSetAttribute(aggregate_kernel, cudaFuncAttributeMaxDynamicSharedMemorySize,
                         A_SMEMF * 4);

    prep_kernel<<<96, 256>>>(w_comp, b_comp, w_enc, b_enc, power_p);
    compress_kernel<<<512, 256, C_SMEMB>>>(x);
    encoder_kernel<<<512, 128, E_SMEMB>>>();
    aggregate_kernel<<<256, 256, A_SMEMF * 4>>>(x, out);
}